// round 10
// baseline (speedup 1.0000x reference)
#include <cuda_runtime.h>
#include <math.h>

#define POOL 7
#define ROI_SCALE 0.0625f
#define WPB 8        // warps per block
#define CH  8        // channels per warp
#define NGR 32       // channel groups = C/CH
#define CMW 66       // smem row pitch (64 cols + 2 pad, even for STS.64)
#define TPR (NGR * POOL)  // warp-tasks per ROI: 32 groups x 7 row-bins = 224

// grid = (TPR/WPB, N) = (28, N). Block owns one ROI: thread 0 decodes the ROI
// geometry once into smem, then each warp handles one (channel-group of 8,
// row-bin) task. Mainloop keeps the register footprint minimal (pointer +
// 16 accumulators); all reduce-role / output-index math happens after the
// loop by re-reading geometry from smem, so launch_bounds(256,5) holds
// without in-loop spills -> 40 warps/SM for latency hiding.
__global__ __launch_bounds__(32 * WPB, 5)
void roipool_kernel(const float* __restrict__ feat,
                    const float* __restrict__ rois,
                    float* __restrict__ out,
                    int N, int C, int write_bid) {
    __shared__ float cm[WPB][CH * CMW];
    __shared__ int g[10];   // b,px,py,qx, lenx,leny, psx,psy, pad0x,pad0y
    const int H = 64, W = 64;

    int n = blockIdx.y;

    // Fused second output of the reference tuple: batch ids as floats.
    if (write_bid && blockIdx.x == 0 && blockIdx.y == 0 && threadIdx.x < N) {
        out[N * C * POOL * POOL + threadIdx.x] =
            (float)((int)rois[threadIdx.x * 5]);
    }

    if (threadIdx.x == 0) {
        const float* r = rois + n * 5;
        // jnp.round = round-half-to-even = __float2int_rn
        int px = __float2int_rn(r[1] * ROI_SCALE);
        int py = __float2int_rn(r[2] * ROI_SCALE);
        int qx = __float2int_rn(r[3] * ROI_SCALE);
        int qy = __float2int_rn(r[4] * ROI_SCALE);
        int lenx = max(qx - px + 1, 1);
        int leny = max(qy - py + 1, 1);
        int psx  = (lenx + POOL - 1) / POOL;
        int psy  = (leny + POOL - 1) / POOL;
        g[0] = (int)r[0];
        g[1] = px; g[2] = py; g[3] = qx;
        g[4] = lenx; g[5] = leny;
        g[6] = psx; g[7] = psy;
        g[8] = (psx * POOL - lenx) / 2;
        g[9] = (psy * POOL - leny) / 2;
    }
    __syncthreads();

    int warp = threadIdx.x >> 5;
    int lane = threadIdx.x & 31;
    int task = blockIdx.x * WPB + warp;   // 0..TPR-1
    int cg   = task & (NGR - 1);          // channel group (8 channels)
    int ph   = task >> 5;                 // row bin 0..6

    // --- minimal prologue for the mainloop ---
    int py_ = g[2], psy = g[7], pad0y = g[9], leny = g[5];
    int ys = max(0, ph * psy - pad0y);
    int ye = min(leny - 1, (ph + 1) * psy - 1 - pad0y);
    bool empty = ys > ye;                 // fully zero-padded row bin

    float2 a0 = make_float2(-INFINITY, -INFINITY);
    float2 a1 = a0, a2 = a0, a3 = a0, a4 = a0, a5 = a0, a6 = a0, a7 = a0;

    if (!empty) {
        int px = g[1], qx = g[3];
        int px2 = px & ~1;                // even-aligned load base
        bool act = (px2 + 2 * lane) <= qx;
        const float2* p = (const float2*)(feat
            + (unsigned)((g[0] * C + cg * CH) * (H * W))
            + (unsigned)((py_ + ys) * W + px2)) + lane;
        const int PL2 = H * W / 2;        // plane stride in float2

#define FM2(d, s) d.x = fmaxf(d.x, s.x); d.y = fmaxf(d.y, s.y)
        for (int ry = ys; ry <= ye; ++ry) {   // 8 LDG.64 in flight per row
            if (act) {
                float2 v0 = __ldg(p);
                float2 v1 = __ldg(p + PL2);
                float2 v2 = __ldg(p + 2 * PL2);
                float2 v3 = __ldg(p + 3 * PL2);
                float2 v4 = __ldg(p + 4 * PL2);
                float2 v5 = __ldg(p + 5 * PL2);
                float2 v6 = __ldg(p + 6 * PL2);
                float2 v7 = __ldg(p + 7 * PL2);
                FM2(a0, v0); FM2(a1, v1); FM2(a2, v2); FM2(a3, v3);
                FM2(a4, v4); FM2(a5, v5); FM2(a6, v6); FM2(a7, v7);
            }
            p += W / 2;
        }
#undef FM2

        // flush column maxima
        float* cw = cm[warp];
        int si = 2 * lane;
        *(float2*)(cw + 0 * CMW + si) = a0;
        *(float2*)(cw + 1 * CMW + si) = a1;
        *(float2*)(cw + 2 * CMW + si) = a2;
        *(float2*)(cw + 3 * CMW + si) = a3;
        *(float2*)(cw + 4 * CMW + si) = a4;
        *(float2*)(cw + 5 * CMW + si) = a5;
        *(float2*)(cw + 6 * CMW + si) = a6;
        *(float2*)(cw + 7 * CMW + si) = a7;
        __syncwarp();
    }

    // --- epilogue: reduce roles computed here (not live across mainloop) ---
    int px = g[1], qx = g[3];
    int lenx = g[4], psx = g[6], pad0x = g[8];
    int dpx = px - (px & ~1);
    bool pady = (ph * psy < pad0y) | ((ph + 1) * psy > pad0y + leny);

    // Each lane owns 2 of the CH*POOL = 56 (ch,pw) outputs: lane and lane+32.
    int ch0 = lane / POOL, pw0 = lane - ch0 * POOL;   // const-div -> mul
    int bi1 = lane + 32;
    int ch1 = bi1 / POOL, pw1 = bi1 - ch1 * POOL;
    bool r1 = bi1 < CH * POOL;
    int ob = (n * C + cg * CH) * (POOL * POOL) + ph * POOL;
    int o0 = ob + ch0 * (POOL * POOL) + pw0;
    int o1 = ob + ch1 * (POOL * POOL) + pw1;

    if (empty) {
        out[o0] = 0.0f;
        if (r1) out[o1] = 0.0f;
        return;
    }

    const float* cw = cm[warp];
    {
        int x0 = pw0 * psx - pad0x;
        int i0 = max(0, -x0);
        int i1 = min(psx, lenx - x0);
        const float* rp = cw + ch0 * CMW + x0 + dpx;
        float mm = -INFINITY;
        for (int i = i0; i < i1; ++i) mm = fmaxf(mm, rp[i]);
        bool padx = (pw0 * psx < pad0x) | ((pw0 + 1) * psx > pad0x + lenx);
        if (padx | pady) mm = fmaxf(mm, 0.0f);
        if (!isfinite(mm)) mm = 0.0f;     // fully-padded bin -> 0
        out[o0] = mm;
    }
    if (r1) {
        int x0 = pw1 * psx - pad0x;
        int i0 = max(0, -x0);
        int i1 = min(psx, lenx - x0);
        const float* rp = cw + ch1 * CMW + x0 + dpx;
        float mm = -INFINITY;
        for (int i = i0; i < i1; ++i) mm = fmaxf(mm, rp[i]);
        bool padx = (pw1 * psx < pad0x) | ((pw1 + 1) * psx > pad0x + lenx);
        if (padx | pady) mm = fmaxf(mm, 0.0f);
        if (!isfinite(mm)) mm = 0.0f;
        out[o1] = mm;
    }
}

extern "C" void kernel_launch(void* const* d_in, const int* in_sizes, int n_in,
                              void* d_out, int out_size) {
    const float* feat = (const float*)d_in[0];
    const float* rois = (const float*)d_in[1];
    float* out = (float*)d_out;

    const int C = 256;
    int N = in_sizes[1] / 5;

    int total = N * C * POOL * POOL;
    int write_bid = (out_size >= total + N) ? 1 : 0;

    dim3 grid(TPR / WPB, N);              // 28 x N blocks
    roipool_kernel<<<grid, 32 * WPB>>>(feat, rois, out, N, C, write_bid);
}

// round 11
// speedup vs baseline: 1.0017x; 1.0017x over previous
#include <cuda_runtime.h>
#include <math.h>

#define POOL 7
#define ROI_SCALE 0.0625f
#define WPB 8        // warps per block
#define CH  8        // channels per warp
#define NGR 32       // channel groups = C/CH
#define CMW 66       // smem row pitch (64 cols + 2 pad, even for STS.64)
#define TPR (NGR * POOL)  // warp-tasks per ROI: 32 groups x 7 row-bins = 224

// grid = (TPR/WPB, N) = (28, N). Block owns one ROI: thread 0 decodes the ROI
// geometry once into smem, then each warp handles one (channel-group of 8,
// row-bin) task. Mainloop keeps the register footprint minimal (pointer +
// 16 accumulators); all reduce-role / output-index math happens after the
// loop by re-reading geometry from smem. launch_bounds(256,6) forces <=40
// regs -> 48 warps/SM, crossing the latency-hiding threshold (~12 warps/SMSP
// needed to cover the ~260-cycle L2 scoreboard between load batches).
__global__ __launch_bounds__(32 * WPB, 6)
void roipool_kernel(const float* __restrict__ feat,
                    const float* __restrict__ rois,
                    float* __restrict__ out,
                    int N, int C, int write_bid) {
    __shared__ float cm[WPB][CH * CMW];
    __shared__ int g[10];   // b,px,py,qx, lenx,leny, psx,psy, pad0x,pad0y
    const int H = 64, W = 64;

    int n = blockIdx.y;

    // Fused second output of the reference tuple: batch ids as floats.
    if (write_bid && blockIdx.x == 0 && blockIdx.y == 0 && threadIdx.x < N) {
        out[N * C * POOL * POOL + threadIdx.x] =
            (float)((int)rois[threadIdx.x * 5]);
    }

    if (threadIdx.x == 0) {
        const float* r = rois + n * 5;
        // jnp.round = round-half-to-even = __float2int_rn
        int px = __float2int_rn(r[1] * ROI_SCALE);
        int py = __float2int_rn(r[2] * ROI_SCALE);
        int qx = __float2int_rn(r[3] * ROI_SCALE);
        int qy = __float2int_rn(r[4] * ROI_SCALE);
        int lenx = max(qx - px + 1, 1);
        int leny = max(qy - py + 1, 1);
        int psx  = (lenx + POOL - 1) / POOL;
        int psy  = (leny + POOL - 1) / POOL;
        g[0] = (int)r[0];
        g[1] = px; g[2] = py; g[3] = qx;
        g[4] = lenx; g[5] = leny;
        g[6] = psx; g[7] = psy;
        g[8] = (psx * POOL - lenx) / 2;
        g[9] = (psy * POOL - leny) / 2;
    }
    __syncthreads();

    int warp = threadIdx.x >> 5;
    int lane = threadIdx.x & 31;
    int task = blockIdx.x * WPB + warp;   // 0..TPR-1
    int cg   = task & (NGR - 1);          // channel group (8 channels)
    int ph   = task >> 5;                 // row bin 0..6

    // --- minimal prologue for the mainloop ---
    int psy = g[7], pad0y = g[9], leny = g[5];
    int ys = max(0, ph * psy - pad0y);
    int ye = min(leny - 1, (ph + 1) * psy - 1 - pad0y);
    bool empty = ys > ye;                 // fully zero-padded row bin

    float2 a0 = make_float2(-INFINITY, -INFINITY);
    float2 a1 = a0, a2 = a0, a3 = a0, a4 = a0, a5 = a0, a6 = a0, a7 = a0;

    if (!empty) {
        int px2 = g[1] & ~1;              // even-aligned load base
        bool act = (px2 + 2 * lane) <= g[3];
        const float2* p = (const float2*)(feat
            + (unsigned)((g[0] * C + cg * CH) * (H * W))
            + (unsigned)((g[2] + ys) * W + px2)) + lane;
        const int PL2 = H * W / 2;        // plane stride in float2

#define FM2(d, s) d.x = fmaxf(d.x, s.x); d.y = fmaxf(d.y, s.y)
        for (int ry = ys; ry <= ye; ++ry) {   // 8 LDG.64 in flight per row
            if (act) {
                float2 v0 = __ldg(p);
                float2 v1 = __ldg(p + PL2);
                float2 v2 = __ldg(p + 2 * PL2);
                float2 v3 = __ldg(p + 3 * PL2);
                float2 v4 = __ldg(p + 4 * PL2);
                float2 v5 = __ldg(p + 5 * PL2);
                float2 v6 = __ldg(p + 6 * PL2);
                float2 v7 = __ldg(p + 7 * PL2);
                FM2(a0, v0); FM2(a1, v1); FM2(a2, v2); FM2(a3, v3);
                FM2(a4, v4); FM2(a5, v5); FM2(a6, v6); FM2(a7, v7);
            }
            p += W / 2;
        }
#undef FM2

        // flush column maxima
        float* cw = cm[warp];
        int si = 2 * lane;
        *(float2*)(cw + 0 * CMW + si) = a0;
        *(float2*)(cw + 1 * CMW + si) = a1;
        *(float2*)(cw + 2 * CMW + si) = a2;
        *(float2*)(cw + 3 * CMW + si) = a3;
        *(float2*)(cw + 4 * CMW + si) = a4;
        *(float2*)(cw + 5 * CMW + si) = a5;
        *(float2*)(cw + 6 * CMW + si) = a6;
        *(float2*)(cw + 7 * CMW + si) = a7;
        __syncwarp();
    }

    // --- epilogue: reduce roles computed here (not live across mainloop) ---
    int px = g[1];
    int lenx = g[4], psx = g[6], pad0x = g[8];
    int dpx = px & 1;                     // px - (px & ~1)
    bool pady = (ph * psy < pad0y) | ((ph + 1) * psy > pad0y + leny);

    // Each lane owns 2 of the CH*POOL = 56 (ch,pw) outputs: lane and lane+32.
    int ch0 = lane / POOL, pw0 = lane - ch0 * POOL;   // const-div -> mul
    int bi1 = lane + 32;
    int ch1 = bi1 / POOL, pw1 = bi1 - ch1 * POOL;
    bool r1 = bi1 < CH * POOL;
    int ob = (n * C + cg * CH) * (POOL * POOL) + ph * POOL;
    int o0 = ob + ch0 * (POOL * POOL) + pw0;
    int o1 = ob + ch1 * (POOL * POOL) + pw1;

    if (empty) {
        out[o0] = 0.0f;
        if (r1) out[o1] = 0.0f;
        return;
    }

    const float* cw = cm[warp];
    {
        int x0 = pw0 * psx - pad0x;
        int i0 = max(0, -x0);
        int i1 = min(psx, lenx - x0);
        const float* rp = cw + ch0 * CMW + x0 + dpx;
        float mm = -INFINITY;
        for (int i = i0; i < i1; ++i) mm = fmaxf(mm, rp[i]);
        bool padx = (pw0 * psx < pad0x) | ((pw0 + 1) * psx > pad0x + lenx);
        if (padx | pady) mm = fmaxf(mm, 0.0f);
        if (!isfinite(mm)) mm = 0.0f;     // fully-padded bin -> 0
        out[o0] = mm;
    }
    if (r1) {
        int x0 = pw1 * psx - pad0x;
        int i0 = max(0, -x0);
        int i1 = min(psx, lenx - x0);
        const float* rp = cw + ch1 * CMW + x0 + dpx;
        float mm = -INFINITY;
        for (int i = i0; i < i1; ++i) mm = fmaxf(mm, rp[i]);
        bool padx = (pw1 * psx < pad0x) | ((pw1 + 1) * psx > pad0x + lenx);
        if (padx | pady) mm = fmaxf(mm, 0.0f);
        if (!isfinite(mm)) mm = 0.0f;
        out[o1] = mm;
    }
}

extern "C" void kernel_launch(void* const* d_in, const int* in_sizes, int n_in,
                              void* d_out, int out_size) {
    const float* feat = (const float*)d_in[0];
    const float* rois = (const float*)d_in[1];
    float* out = (float*)d_out;

    const int C = 256;
    int N = in_sizes[1] / 5;

    int total = N * C * POOL * POOL;
    int write_bid = (out_size >= total + N) ? 1 : 0;

    dim3 grid(TPR / WPB, N);              // 28 x N blocks
    roipool_kernel<<<grid, 32 * WPB>>>(feat, rois, out, N, C, write_bid);
}